// round 16
// baseline (speedup 1.0000x reference)
#include <cuda_runtime.h>
#include <cstdint>

#define D        64
#define MT       128         // x rows per CTA
#define NC       128         // codes per chunk (64B/code -> 8KB slot)
#define TPB      160         // 4 consumer warps + 1 producer warp
#define MAXM     4096
#define RING     3
#define QSCALE   25.0f

__device__ __align__(16) int8_t g_codes_s8[MAXM * D];
__device__ __align__(16) int     g_c2i[MAXM];    // (||c_q||^2) >> 1

static __device__ __forceinline__ uint32_t su32(const void* p) {
    uint32_t a;
    asm("{ .reg .u64 t; cvta.to.shared.u64 t, %1; cvt.u32.u64 %0, t; }" : "=r"(a) : "l"(p));
    return a;
}
static __device__ __forceinline__ int q8(float v) {
    int q = __float2int_rn(v * QSCALE);
    return max(-127, min(127, q));
}
static __device__ __forceinline__ uint32_t pack4(int a, int b, int c, int d) {
    return (uint32_t)(a & 0xFF) | ((uint32_t)(b & 0xFF) << 8) |
           ((uint32_t)(c & 0xFF) << 16) | ((uint32_t)d << 24);
}

#define LDSM4(r0, r1, r2, r3, addr)                                                   \
    asm volatile("ldmatrix.sync.aligned.m8n8.x4.shared.b16 {%0,%1,%2,%3}, [%4];"      \
                 : "=r"(r0), "=r"(r1), "=r"(r2), "=r"(r3) : "r"(addr))

// s8 IMMA, s32 accum, acc in-place
#define MMA_S8(dd, a, b0, b1)                                                         \
    asm volatile("mma.sync.aligned.m16n8k32.row.col.s32.s8.s8.s32 "                   \
                 "{%0,%1,%2,%3},{%4,%5,%6,%7},{%8,%9},{%0,%1,%2,%3};"                 \
                 : "+r"((dd)[0]), "+r"((dd)[1]), "+r"((dd)[2]), "+r"((dd)[3])         \
                 : "r"((a)[0]), "r"((a)[1]), "r"((a)[2]), "r"((a)[3]),                \
                   "r"(b0), "r"(b1))

#define CPASYNC16(saddr, gptr)                                                        \
    asm volatile("cp.async.cg.shared.global [%0], [%1], 16;" :: "r"(saddr), "l"(gptr))
#define CPWAIT0()  asm volatile("cp.async.wait_group 0;")
#define CPASYNC_MBAR_ARRIVE(mbar)                                                     \
    asm volatile("cp.async.mbarrier.arrive.noinc.shared.b64 [%0];" :: "r"(mbar) : "memory")
#define MBARRIER_INIT(mbar, cnt)                                                      \
    asm volatile("mbarrier.init.shared.b64 [%0], %1;" :: "r"(mbar), "r"(cnt) : "memory")
#define MBARRIER_ARRIVE(mbar)                                                         \
    asm volatile("mbarrier.arrive.shared.b64 _, [%0];" :: "r"(mbar) : "memory")
#define MBARRIER_WAIT_PARITY(mbar, parity) do {                                       \
    uint32_t _m = (mbar), _p = (parity), _done;                                       \
    asm volatile("{\n\t.reg .pred p;\n\t"                                             \
        "mbarrier.try_wait.parity.acquire.cta.shared::cta.b64 p, [%1], %2;\n\t"       \
        "selp.b32 %0, 1, 0, p;\n\t}"                                                  \
        : "=r"(_done) : "r"(_m), "r"(_p) : "memory");                                 \
    if (!_done) {                                                                     \
        asm volatile("{\n\t.reg .pred P1;\n\t"                                        \
            "WL_%=:\n\t"                                                              \
            "mbarrier.try_wait.parity.acquire.cta.shared::cta.b64 P1, [%0], %1, 0x989680;\n\t" \
            "@P1 bra.uni WD_%=;\n\t"                                                  \
            "bra.uni WL_%=;\n\t"                                                      \
            "WD_%=:\n\t}" :: "r"(_m), "r"(_p) : "memory");                            \
    }                                                                                 \
} while (0)

// 64B-row swizzle: row r, 16B-chunk kb (0..3) — conflict-free for ldmatrix
static __device__ __forceinline__ uint32_t sw64(int row, int kb) {
    return (uint32_t)row * 64u + (uint32_t)((kb ^ ((row >> 1) & 3)) << 4);
}

// ---------------- prep: codes -> s8 + (||c_q||^2)>>1 ----------------
__global__ void prep_kernel(const float* __restrict__ codes, int M) {
    int gid = blockIdx.x * blockDim.x + threadIdx.x;
    int m = gid >> 4, seg = gid & 15;
    if (m >= M) return;
    float4 v = __ldg(reinterpret_cast<const float4*>(codes + (size_t)m * D) + seg);
    int q0 = q8(v.x), q1 = q8(v.y), q2 = q8(v.z), q3 = q8(v.w);
    int s = q0 * q0 + q1 * q1 + q2 * q2 + q3 * q3;
    s += __shfl_xor_sync(0xFFFFFFFFu, s, 1);
    s += __shfl_xor_sync(0xFFFFFFFFu, s, 2);
    s += __shfl_xor_sync(0xFFFFFFFFu, s, 4);
    s += __shfl_xor_sync(0xFFFFFFFFu, s, 8);
    reinterpret_cast<uint32_t*>(g_codes_s8)[m * 16 + seg] = pack4(q0, q1, q2, q3);
    if (seg == 0) g_c2i[m] = s >> 1;
}

// ---------------- main kernel ----------------
__global__ __launch_bounds__(TPB, 4) void nn_mma_kernel(
    const float* __restrict__ x, const float* __restrict__ codes,
    float* __restrict__ out, int M)
{
    __shared__ __align__(128) unsigned char smRing[RING * NC * 64];  // 24KB
    __shared__ __align__(128) unsigned char smA[MT * 64];            // 8KB
    __shared__ __align__(8)   unsigned char smBar[2 * RING * 8];
    __shared__ float sD2[MT];

    const int t = threadIdx.x;
    const int L = t & 31;
    const int w = t >> 5;
    const int CHUNKS = M / NC;        // 32

    const uint32_t ringB  = su32(smRing);
    const uint32_t sAb    = su32(smA);
    const uint32_t fullB  = su32(smBar);
    const uint32_t emptyB = fullB + RING * 8;

    if (t == 0) {
#pragma unroll
        for (int s = 0; s < RING; s++) {
            MBARRIER_INIT(fullB  + s * 8, 32);
            MBARRIER_INIT(emptyB + s * 8, 128);
        }
    }

    // ---- consumer threads: quantize x row t -> s8 into smA (swizzled); x2q exact ----
    int x2q = 0;
    if (t < MT) {
        const float4* xr = reinterpret_cast<const float4*>(
            x + ((size_t)blockIdx.x * MT + t) * D);
#pragma unroll
        for (int kb = 0; kb < 4; kb++) {
            uint32_t qw[4];
#pragma unroll
            for (int j = 0; j < 4; j++) {
                float4 v = xr[4 * kb + j];
                int q0 = q8(v.x), q1 = q8(v.y), q2 = q8(v.z), q3 = q8(v.w);
                x2q += q0 * q0 + q1 * q1 + q2 * q2 + q3 * q3;
                qw[j] = pack4(q0, q1, q2, q3);
            }
            *reinterpret_cast<uint4*>(smA + sw64(t, kb)) =
                make_uint4(qw[0], qw[1], qw[2], qw[3]);
        }
    }
    __syncthreads();      // A staged + mbarriers initialized

    if (w == 4) {
        // ================= producer warp =================
        int es = 0, ep = 1;
#pragma unroll 1
        for (int ch = 0; ch < CHUNKS; ch++) {
            MBARRIER_WAIT_PARITY(emptyB + es * 8, ep);
            const uint32_t dst = ringB + (uint32_t)es * (NC * 64);
            const char* src = reinterpret_cast<const char*>(g_codes_s8) + (size_t)ch * (NC * 64);
#pragma unroll
            for (int i = 0; i < 16; i++) {
                int idx = L + i * 32;          // 512 x 16B = 8KB
                int n = idx >> 2, kb = idx & 3;
                CPASYNC16(dst + sw64(n, kb), src + idx * 16);
            }
            CPASYNC_MBAR_ARRIVE(fullB + es * 8);
            if (++es == RING) { es = 0; ep ^= 1; }
        }
        CPWAIT0();
        return;
    }

    // ================= consumer warps (0-3) =================
    // A fragments: warp w owns rows w*32..w*32+31; [mt][ks][4]
    uint32_t Af[2][2][4];
    const int mbw = w * 32;
#pragma unroll
    for (int mt = 0; mt < 2; mt++)
#pragma unroll
        for (int ks = 0; ks < 2; ks++) {
            int r  = mbw + mt * 16 + (L & 15);
            int kb = ks * 2 + (L >> 4);
            LDSM4(Af[mt][ks][0], Af[mt][ks][1], Af[mt][ks][2], Af[mt][ks][3],
                  sAb + sw64(r, kb));
        }

    const int g  = L >> 2;
    const int tc = L & 3;
    const int rB = L & 7;        // B row within ntile
    const int kB = L >> 3;       // B 16B-chunk (0..3)

    int kmax[2][2] = {{INT_MIN, INT_MIN}, {INT_MIN, INT_MIN}};

    int fs = 0, fp = 0;
#pragma unroll 1
    for (int ch = 0; ch < CHUNKS; ch++) {
        const int cb = ch * NC;

        MBARRIER_WAIT_PARITY(fullB + fs * 8, fp);
        const uint32_t sBc = ringB + (uint32_t)fs * (NC * 64);

        // LDSM double buffer over nt pairs
        uint32_t f[2][8];
        int2 c2n[2][2];
        {
            LDSM4(f[0][0], f[0][1], f[0][2], f[0][3], sBc + sw64(0 * 8 + rB, kB));
            LDSM4(f[0][4], f[0][5], f[0][6], f[0][7], sBc + sw64(1 * 8 + rB, kB));
            c2n[0][0] = __ldg(reinterpret_cast<const int2*>(g_c2i + cb + 0 * 8 + tc * 2));
            c2n[0][1] = __ldg(reinterpret_cast<const int2*>(g_c2i + cb + 1 * 8 + tc * 2));
        }

#pragma unroll
        for (int np = 0; np < 8; np++) {        // nt = 2np, 2np+1
            const int cur = np & 1, nxt = cur ^ 1;
            if (np < 7) {
                LDSM4(f[nxt][0], f[nxt][1], f[nxt][2], f[nxt][3],
                      sBc + sw64((2 * np + 2) * 8 + rB, kB));
                LDSM4(f[nxt][4], f[nxt][5], f[nxt][6], f[nxt][7],
                      sBc + sw64((2 * np + 3) * 8 + rB, kB));
                c2n[nxt][0] = __ldg(reinterpret_cast<const int2*>(g_c2i + cb + (2 * np + 2) * 8 + tc * 2));
                c2n[nxt][1] = __ldg(reinterpret_cast<const int2*>(g_c2i + cb + (2 * np + 3) * 8 + tc * 2));
            }

            // acc: [ni][mt][4], init = -c2half (so result = S - c2/2)
            int acc[2][2][4];
#pragma unroll
            for (int ni = 0; ni < 2; ni++)
#pragma unroll
                for (int mt = 0; mt < 2; mt++) {
                    acc[ni][mt][0] = -c2n[cur][ni].x;
                    acc[ni][mt][1] = -c2n[cur][ni].y;
                    acc[ni][mt][2] = -c2n[cur][ni].x;
                    acc[ni][mt][3] = -c2n[cur][ni].y;
                }

            const uint32_t* b = f[cur];
            // ks0: regs {b[0],b[1]} (nt even), {b[4],b[5]} (nt odd); ks1: {b[2],b[3]}, {b[6],b[7]}
            MMA_S8(acc[0][0], Af[0][0], b[0], b[1]);
            MMA_S8(acc[0][1], Af[1][0], b[0], b[1]);
            MMA_S8(acc[1][0], Af[0][0], b[4], b[5]);
            MMA_S8(acc[1][1], Af[1][0], b[4], b[5]);
            MMA_S8(acc[0][0], Af[0][1], b[2], b[3]);
            MMA_S8(acc[0][1], Af[1][1], b[2], b[3]);
            MMA_S8(acc[1][0], Af[0][1], b[6], b[7]);
            MMA_S8(acc[1][1], Af[1][1], b[6], b[7]);

            // epilogue: running max of (S - c2/2)
#pragma unroll
            for (int ni = 0; ni < 2; ni++)
#pragma unroll
                for (int mt = 0; mt < 2; mt++) {
                    kmax[mt][0] = max(kmax[mt][0], max(acc[ni][mt][0], acc[ni][mt][1]));
                    kmax[mt][1] = max(kmax[mt][1], max(acc[ni][mt][2], acc[ni][mt][3]));
                }
        }

        MBARRIER_ARRIVE(emptyB + fs * 8);
        if (++fs == RING) { fs = 0; fp ^= 1; }
    }

    // ---- reduce across 4 tc lanes; min d_q^2 (int units) = x2q - 2*max ----
#pragma unroll
    for (int mt = 0; mt < 2; mt++)
#pragma unroll
        for (int h = 0; h < 2; h++) {
            int v = kmax[mt][h];
            v = max(v, __shfl_xor_sync(0xFFFFFFFFu, v, 1));
            v = max(v, __shfl_xor_sync(0xFFFFFFFFu, v, 2));
            int x2row = __shfl_sync(0xFFFFFFFFu, x2q, mt * 16 + h * 8 + g);
            if (tc == 0)
                sD2[mbw + mt * 16 + h * 8 + g] = (float)(x2row - 2 * v);
        }
    asm volatile("bar.sync 1, 128;" ::: "memory");   // consumer threads only

    // ---- fused finalize: thread t owns row t ----
    {
        const int row = blockIdx.x * MT + t;
        float d2i = sD2[t];
        float res = -1.0f;
        // flag threshold 15626 int units = d_q^2 <= 25.0; |d - d_q| <= 0.33 => safe
        if (d2i <= 15626.0f) {
            const float* xr = x + (size_t)row * D;
            float best = 3.4e38f;
            int   bi = 0;
#pragma unroll 1
            for (int m = 0; m < M; m++) {
                const float* c = codes + (size_t)m * D;
                float s = 0.f;
#pragma unroll 4
                for (int i = 0; i < D; i++) {
                    float dd = __ldg(xr + i) - __ldg(c + i);
                    s = fmaf(dd, dd, s);
                }
                if (s < best) { best = s; bi = m; }
            }
            if (best <= 0.1f) res = (float)bi;
        }
        out[row] = res;
    }
}

extern "C" void kernel_launch(void* const* d_in, const int* in_sizes, int n_in,
                              void* d_out, int out_size) {
    const float* x     = (const float*)d_in[0];
    const float* codes = (const float*)d_in[1];
    float*       out   = (float*)d_out;

    const int M     = in_sizes[1] / D;     // 4096
    const int nRows = in_sizes[0] / D;     // 65536

    prep_kernel<<<(M * 16) / 256, 256>>>(codes, M);
    nn_mma_kernel<<<nRows / MT, TPB>>>(x, codes, out, M);
}

// round 17
// speedup vs baseline: 5.2710x; 5.2710x over previous
#include <cuda_runtime.h>
#include <cuda_fp16.h>
#include <cstdint>

#define D        64
#define KS       32          // screened dims (first 32 of 64)
#define MT       128         // x rows per CTA
#define NC       128         // codes per chunk (64B/code -> 8KB slot)
#define TPB      160         // 4 consumer warps + 1 producer warp
#define MAXM     4096
#define RING     3

__device__ __align__(16) __half g_codes_f16[MAXM * KS];   // 256KB: first 32 dims
__device__ __align__(16) __half g_c2h[MAXM];              // fp16(-||c_32||^2 / 2)

static __device__ __forceinline__ uint32_t su32(const void* p) {
    uint32_t a;
    asm("{ .reg .u64 t; cvta.to.shared.u64 t, %1; cvt.u32.u64 %0, t; }" : "=r"(a) : "l"(p));
    return a;
}
static __device__ __forceinline__ uint32_t h2u(__half2 h) {
    return *reinterpret_cast<uint32_t*>(&h);
}
static __device__ __forceinline__ __half2 u2h(uint32_t u) {
    return *reinterpret_cast<__half2*>(&u);
}

#define LDSM4(r0, r1, r2, r3, addr)                                                   \
    asm volatile("ldmatrix.sync.aligned.m8n8.x4.shared.b16 {%0,%1,%2,%3}, [%4];"      \
                 : "=r"(r0), "=r"(r1), "=r"(r2), "=r"(r3) : "r"(addr))

#define MMA16816H(c0, c1, a, b0, b1)                                                  \
    asm volatile("mma.sync.aligned.m16n8k16.row.col.f16.f16.f16.f16 "                 \
                 "{%0,%1},{%2,%3,%4,%5},{%6,%7},{%0,%1};"                             \
                 : "+r"(c0), "+r"(c1)                                                 \
                 : "r"((a)[0]), "r"((a)[1]), "r"((a)[2]), "r"((a)[3]),                \
                   "r"(b0), "r"(b1))

#define CPASYNC16(saddr, gptr)                                                        \
    asm volatile("cp.async.cg.shared.global [%0], [%1], 16;" :: "r"(saddr), "l"(gptr))
#define CPWAIT0()  asm volatile("cp.async.wait_group 0;")
#define CPASYNC_MBAR_ARRIVE(mbar)                                                     \
    asm volatile("cp.async.mbarrier.arrive.noinc.shared.b64 [%0];" :: "r"(mbar) : "memory")
#define MBARRIER_INIT(mbar, cnt)                                                      \
    asm volatile("mbarrier.init.shared.b64 [%0], %1;" :: "r"(mbar), "r"(cnt) : "memory")
#define MBARRIER_ARRIVE(mbar)                                                         \
    asm volatile("mbarrier.arrive.shared.b64 _, [%0];" :: "r"(mbar) : "memory")
#define MBARRIER_WAIT_PARITY(mbar, parity) do {                                       \
    uint32_t _m = (mbar), _p = (parity), _done;                                       \
    asm volatile("{\n\t.reg .pred p;\n\t"                                             \
        "mbarrier.try_wait.parity.acquire.cta.shared::cta.b64 p, [%1], %2;\n\t"       \
        "selp.b32 %0, 1, 0, p;\n\t}"                                                  \
        : "=r"(_done) : "r"(_m), "r"(_p) : "memory");                                 \
    if (!_done) {                                                                     \
        asm volatile("{\n\t.reg .pred P1;\n\t"                                        \
            "WL_%=:\n\t"                                                              \
            "mbarrier.try_wait.parity.acquire.cta.shared::cta.b64 P1, [%0], %1, 0x989680;\n\t" \
            "@P1 bra.uni WD_%=;\n\t"                                                  \
            "bra.uni WL_%=;\n\t"                                                      \
            "WD_%=:\n\t}" :: "r"(_m), "r"(_p) : "memory");                            \
    }                                                                                 \
} while (0)

// 64B-row swizzle: row r, 16B-chunk kb (0..3) — ldmatrix conflict-free
static __device__ __forceinline__ uint32_t sw64(int row, int kb) {
    return (uint32_t)row * 64u + (uint32_t)((kb ^ ((row >> 1) & 3)) << 4);
}

// ---------------- prep: first-32-dims -> f16 + fp16(-||c32||^2/2) ----------------
__global__ void prep_kernel(const float* __restrict__ codes, int M) {
    int gid = blockIdx.x * blockDim.x + threadIdx.x;
    int m = gid >> 4, seg = gid & 15;
    if (m >= M) return;
    float s = 0.f;
    if (seg < 8) {   // dims 4*seg .. 4*seg+3, all < 32
        float4 v = __ldg(reinterpret_cast<const float4*>(codes + (size_t)m * D) + seg);
        s = v.x * v.x + v.y * v.y + v.z * v.z + v.w * v.w;
        uint2 u;
        u.x = h2u(__floats2half2_rn(v.x, v.y));
        u.y = h2u(__floats2half2_rn(v.z, v.w));
        reinterpret_cast<uint2*>(g_codes_f16 + (size_t)m * KS)[seg] = u;
    }
    s += __shfl_xor_sync(0xFFFFFFFFu, s, 1);
    s += __shfl_xor_sync(0xFFFFFFFFu, s, 2);
    s += __shfl_xor_sync(0xFFFFFFFFu, s, 4);
    s += __shfl_xor_sync(0xFFFFFFFFu, s, 8);
    if (seg == 0) g_c2h[m] = __float2half_rn(-0.5f * s);
}

// ---------------- main kernel ----------------
__global__ __launch_bounds__(TPB, 4) void nn_mma_kernel(
    const float* __restrict__ x, const float* __restrict__ codes,
    float* __restrict__ out, int M)
{
    __shared__ __align__(128) unsigned char smRing[RING * NC * 64];  // 24KB
    __shared__ __align__(128) unsigned char smA[MT * 64];            // 8KB
    __shared__ __align__(8)   unsigned char smBar[2 * RING * 8];
    __shared__ float sD2[MT];

    const int t = threadIdx.x;
    const int L = t & 31;
    const int w = t >> 5;
    const int CHUNKS = M / NC;        // 32

    const uint32_t ringB  = su32(smRing);
    const uint32_t sAb    = su32(smA);
    const uint32_t fullB  = su32(smBar);
    const uint32_t emptyB = fullB + RING * 8;

    if (t == 0) {
#pragma unroll
        for (int s = 0; s < RING; s++) {
            MBARRIER_INIT(fullB  + s * 8, 32);
            MBARRIER_INIT(emptyB + s * 8, 128);
        }
    }

    // ---- consumer threads stage x rows (first 32 dims) into smA; x2_32 in reg ----
    float x2 = 0.f;
    if (t < MT) {
        const float4* xr = reinterpret_cast<const float4*>(
            x + ((size_t)blockIdx.x * MT + t) * D);
#pragma unroll
        for (int kb = 0; kb < 4; kb++) {
            float4 f0 = xr[2 * kb], f1 = xr[2 * kb + 1];   // dims 8kb .. 8kb+7 (<32)
            x2 += f0.x * f0.x + f0.y * f0.y + f0.z * f0.z + f0.w * f0.w;
            x2 += f1.x * f1.x + f1.y * f1.y + f1.z * f1.z + f1.w * f1.w;
            uint4 u;
            u.x = h2u(__floats2half2_rn(f0.x, f0.y));
            u.y = h2u(__floats2half2_rn(f0.z, f0.w));
            u.z = h2u(__floats2half2_rn(f1.x, f1.y));
            u.w = h2u(__floats2half2_rn(f1.z, f1.w));
            *reinterpret_cast<uint4*>(smA + sw64(t, kb)) = u;
        }
    }
    __syncthreads();      // A staged + mbarriers initialized

    if (w == 4) {
        // ================= producer warp =================
        int es = 0, ep = 1;
#pragma unroll 1
        for (int ch = 0; ch < CHUNKS; ch++) {
            MBARRIER_WAIT_PARITY(emptyB + es * 8, ep);
            const uint32_t dst = ringB + (uint32_t)es * (NC * 64);
            const char* src = reinterpret_cast<const char*>(g_codes_f16) + (size_t)ch * (NC * 64);
#pragma unroll
            for (int i = 0; i < 16; i++) {
                int idx = L + i * 32;          // 512 x 16B = 8KB
                int n = idx >> 2, kb = idx & 3;
                CPASYNC16(dst + sw64(n, kb), src + idx * 16);
            }
            CPASYNC_MBAR_ARRIVE(fullB + es * 8);
            if (++es == RING) { es = 0; ep ^= 1; }
        }
        CPWAIT0();
        return;
    }

    // ================= consumer warps (0-3) =================
    // A fragments: [mt][ks][4]; warp w owns rows w*32..w*32+31
    uint32_t Af[2][2][4];
    const int mbw = w * 32;
#pragma unroll
    for (int mt = 0; mt < 2; mt++)
#pragma unroll
        for (int ks = 0; ks < 2; ks++) {
            int r  = mbw + mt * 16 + (L & 15);
            int kb = 2 * ks + (L >> 4);
            LDSM4(Af[mt][ks][0], Af[mt][ks][1], Af[mt][ks][2], Af[mt][ks][3],
                  sAb + sw64(r, kb));
        }

    const int g   = L >> 2;
    const int tc  = L & 3;
    const int rrb = (L & 7) + ((L >> 4) << 3);
    const int kbb = (L >> 3) & 1;

    __half2 kmax[2][2];
#pragma unroll
    for (int a = 0; a < 2; a++)
#pragma unroll
        for (int b = 0; b < 2; b++) kmax[a][b] = __floats2half2_rn(-65504.f, -65504.f);

    int fs = 0, fp = 0;
#pragma unroll 1
    for (int ch = 0; ch < CHUNKS; ch++) {
        const int cb = ch * NC;

        // hoisted: -c2/2 for 16 n-tiles (this lane's 2 cols each)
        uint32_t c2v[8][2];
#pragma unroll
        for (int p = 0; p < 8; p++) {
            c2v[p][0] = __ldg(reinterpret_cast<const uint32_t*>(g_c2h + cb + (2 * p) * 8 + tc * 2));
            c2v[p][1] = __ldg(reinterpret_cast<const uint32_t*>(g_c2h + cb + (2 * p + 1) * 8 + tc * 2));
        }

        MBARRIER_WAIT_PARITY(fullB + fs * 8, fp);
        const uint32_t sBc = ringB + (uint32_t)fs * (NC * 64);

#pragma unroll
        for (int pp = 0; pp < 8; pp++) {        // nt pair (2pp, 2pp+1)
            uint32_t acc[2][2][2];              // [mt][nt][reg]
#pragma unroll
            for (int mt = 0; mt < 2; mt++)
#pragma unroll
                for (int nt = 0; nt < 2; nt++) {
                    acc[mt][nt][0] = c2v[pp][nt];
                    acc[mt][nt][1] = c2v[pp][nt];
                }

            const int rr = pp * 16 + rrb;
            uint32_t f0[4], f1[4];
            LDSM4(f0[0], f0[1], f0[2], f0[3], sBc + sw64(rr, kbb));        // k-step 0
            LDSM4(f1[0], f1[1], f1[2], f1[3], sBc + sw64(rr, 2 + kbb));    // k-step 1

            MMA16816H(acc[0][0][0], acc[0][0][1], Af[0][0], f0[0], f0[1]);
            MMA16816H(acc[0][1][0], acc[0][1][1], Af[0][0], f0[2], f0[3]);
            MMA16816H(acc[1][0][0], acc[1][0][1], Af[1][0], f0[0], f0[1]);
            MMA16816H(acc[1][1][0], acc[1][1][1], Af[1][0], f0[2], f0[3]);
            MMA16816H(acc[0][0][0], acc[0][0][1], Af[0][1], f1[0], f1[1]);
            MMA16816H(acc[0][1][0], acc[0][1][1], Af[0][1], f1[2], f1[3]);
            MMA16816H(acc[1][0][0], acc[1][0][1], Af[1][1], f1[0], f1[1]);
            MMA16816H(acc[1][1][0], acc[1][1][1], Af[1][1], f1[2], f1[3]);

#pragma unroll
            for (int mt = 0; mt < 2; mt++)
#pragma unroll
                for (int nt = 0; nt < 2; nt++) {
                    kmax[mt][0] = __hmax2(kmax[mt][0], u2h(acc[mt][nt][0]));
                    kmax[mt][1] = __hmax2(kmax[mt][1], u2h(acc[mt][nt][1]));
                }
        }

        MBARRIER_ARRIVE(emptyB + fs * 8);
        if (++fs == RING) { fs = 0; fp ^= 1; }
    }

    // ---- reduce across 4 tc lanes; approx min d^2_32 = x2_32 - 2*max ----
#pragma unroll
    for (int mt = 0; mt < 2; mt++)
#pragma unroll
        for (int h = 0; h < 2; h++) {
            uint32_t k = h2u(kmax[mt][h]);
            k = h2u(__hmax2(u2h(k), u2h(__shfl_xor_sync(0xFFFFFFFFu, k, 1))));
            k = h2u(__hmax2(u2h(k), u2h(__shfl_xor_sync(0xFFFFFFFFu, k, 2))));
            float x2row = __shfl_sync(0xFFFFFFFFu, x2, mt * 16 + h * 8 + g);
            if (tc == 0) {
                __half2 v = u2h(k);
                float smax = fmaxf(__half2float(__low2half(v)), __half2float(__high2half(v)));
                sD2[mbw + mt * 16 + h * 8 + g] = fmaf(smax, -2.f, x2row);
            }
        }
    asm volatile("bar.sync 1, 128;" ::: "memory");   // consumer threads only

    // ---- finalize: flag iff approx d2_32 <= 2.0; warp-cooperative exact rescan ----
    {
        float d2a = sD2[t];
        float res = -1.0f;
        unsigned need = __ballot_sync(0xFFFFFFFFu, d2a <= 2.0f);
        while (need) {
            int lr = __ffs(need) - 1;
            need &= need - 1;
            const int rrow = blockIdx.x * MT + (w << 5) + lr;
            const float* xr = x + (size_t)rrow * D;
            float best = 3.4e38f;
            int   bi = 0x7FFFFFFF;
#pragma unroll 1
            for (int m = L; m < M; m += 32) {
                const float* c = codes + (size_t)m * D;
                float s = 0.f;
#pragma unroll 8
                for (int i = 0; i < D; i++) {
                    float dd = __ldg(xr + i) - __ldg(c + i);
                    s = fmaf(dd, dd, s);
                }
                if (s < best) { best = s; bi = m; }
            }
#pragma unroll
            for (int off = 16; off; off >>= 1) {
                float ob = __shfl_xor_sync(0xFFFFFFFFu, best, off);
                int   oi = __shfl_xor_sync(0xFFFFFFFFu, bi, off);
                if (ob < best || (ob == best && oi < bi)) { best = ob; bi = oi; }
            }
            if (L == lr) res = (best <= 0.1f) ? (float)bi : -1.0f;
        }
        out[(size_t)blockIdx.x * MT + t] = res;
    }
}

extern "C" void kernel_launch(void* const* d_in, const int* in_sizes, int n_in,
                              void* d_out, int out_size) {
    const float* x     = (const float*)d_in[0];
    const float* codes = (const float*)d_in[1];
    float*       out   = (float*)d_out;

    const int M     = in_sizes[1] / D;     // 4096
    const int nRows = in_sizes[0] / D;     // 65536

    prep_kernel<<<(M * 16) / 256, 256>>>(codes, M);
    nn_mma_kernel<<<nRows / MT, TPB>>>(x, codes, out, M);
}